// round 11
// baseline (speedup 1.0000x reference)
#include <cuda_runtime.h>
#include <cuda_fp16.h>
#include <cstdint>
#include <cstddef>

#define DI __device__ __forceinline__

// ---------------- problem constants ----------------
constexpr int BATCH = 4096;
constexpr int INF   = 1024;
constexpr int OUTF  = 1024;
constexpr int KSP   = INF * 8;       // 8192 spline K
constexpr int KTOT  = KSP + INF;     // 9216 total K
constexpr int KBLK  = 64;            // fp16 per K-tile -> 128 B rows (SW128)
constexpr int NKT   = KTOT / KBLK;   // 144 K-tiles
constexpr int TM    = 128;
constexpr int TN    = 256;           // proven best: operand reuse beats occupancy
constexpr int MT    = BATCH / TM;    // 32
constexpr int NT    = OUTF / TN;     // 4
constexpr int STAGES = 4;
constexpr int A_TILE_B = TM * KBLK * 2;       // 16384
constexpr int B_TILE_B = TN * KBLK * 2;       // 32768
constexpr int STAGE_B  = A_TILE_B + B_TILE_B; // 49152

constexpr int NTHREADS = 288;    // 8 consumer warps + 1 producer warp

constexpr int SOFF_FULL  = 0;    // 4 x 8B
constexpr int SOFF_EMPTY = 32;   // 4 x 8B
constexpr int SOFF_STAGE = 1024;
constexpr int SMEM_NEED  = 1024 + SOFF_STAGE + STAGES * STAGE_B; // 198656 < 227KB cap

constexpr int BLOCKS_A = (BATCH * INF) / 256;       // 16384
constexpr int BLOCKS_B = (OUTF * (KTOT / 8)) / 256; // 4608

// ---------------- scratch (device globals; no allocation) ----------------
__device__ __half g_A[(size_t)MT * NKT * TM * KBLK];  // 75.5 MB tiled+swizzled activations
__device__ __half g_B[(size_t)NT * NKT * TN * KBLK];  // 18.9 MB tiled+swizzled weights

// ---------------- PTX helpers ----------------
DI uint32_t s2u(const void* p) {
    uint32_t a;
    asm("{ .reg .u64 t; cvta.to.shared.u64 t, %1; cvt.u32.u64 %0, t; }" : "=r"(a) : "l"(p));
    return a;
}
DI uint32_t swz(uint32_t off) { return off ^ ((off >> 3) & 0x70); }

DI void mbar_init(uint32_t a, uint32_t cnt) {
    asm volatile("mbarrier.init.shared.b64 [%0], %1;" :: "r"(a), "r"(cnt) : "memory");
}
DI void mbar_arrive(uint32_t a) {
    asm volatile("mbarrier.arrive.release.cta.shared.b64 _, [%0];" :: "r"(a) : "memory");
}
DI void mbar_expect_tx(uint32_t a, uint32_t bytes) {
    asm volatile("mbarrier.arrive.expect_tx.shared.b64 _, [%0], %1;" :: "r"(a), "r"(bytes) : "memory");
}
DI void mbar_wait(uint32_t a, uint32_t parity) {
    asm volatile(
        "{\n\t"
        ".reg .pred P1;\n\t"
        "WAIT_LOOP_%=:\n\t"
        "mbarrier.try_wait.parity.acquire.cta.shared::cta.b64 P1, [%0], %1, 0x989680;\n\t"
        "@P1 bra.uni WAIT_DONE_%=;\n\t"
        "bra.uni WAIT_LOOP_%=;\n\t"
        "WAIT_DONE_%=:\n\t"
        "}"
        :: "r"(a), "r"(parity) : "memory");
}
DI void bulk_g2s(uint32_t dst, const void* src, uint32_t bytes, uint32_t mbar) {
    asm volatile(
        "cp.async.bulk.shared::cluster.global.mbarrier::complete_tx::bytes [%0], [%1], %2, [%3];"
        :: "r"(dst), "l"(src), "r"(bytes), "r"(mbar) : "memory");
}
DI void ldsm4(uint32_t* r, uint32_t addr) {
    asm volatile("ldmatrix.sync.aligned.m8n8.x4.shared.b16 {%0,%1,%2,%3}, [%4];"
                 : "=r"(r[0]), "=r"(r[1]), "=r"(r[2]), "=r"(r[3]) : "r"(addr));
}
DI void mma_f16(float* c, const uint32_t* a, uint32_t b0, uint32_t b1) {
    asm volatile(
        "mma.sync.aligned.m16n8k16.row.col.f32.f16.f16.f32 "
        "{%0,%1,%2,%3}, {%4,%5,%6,%7}, {%8,%9}, {%0,%1,%2,%3};"
        : "+f"(c[0]), "+f"(c[1]), "+f"(c[2]), "+f"(c[3])
        : "r"(a[0]), "r"(a[1]), "r"(a[2]), "r"(a[3]), "r"(b0), "r"(b1));
}

// ---------------- merged prologue: A (closed-form bases + silu) and B ----------------
__global__ void __launch_bounds__(256) prolog_ab(const float* __restrict__ x,
                                                 const float* __restrict__ spw,
                                                 const float* __restrict__ baw) {
    if (blockIdx.x < BLOCKS_A) {
        // ----- part A: one (b, i) per thread -----
        int idx = blockIdx.x * 256 + threadIdx.x;
        int b = idx >> 10;
        int i = idx & 1023;
        float xv = x[idx];

        // tanh(x) = 1 - 2/(e^{2x}+1)
        float t = 1.0f - __fdividef(2.0f, __expf(2.0f * xv) + 1.0f);

        // closed-form cubic B-spline: only 4 nonzero bases
        float sc = (t + 2.2f) * 2.5f;                  // interval coord, in [3, 8]
        int m = __float2int_rd(sc);
        m = max(3, min(7, m));                          // clamp (t = +-1 edges)
        float u = sc - (float)m;                        // [0, 1)
        float omu = 1.0f - u;
        float B0 = omu * omu * omu * (1.0f / 6.0f);
        float B3 = u * u * u * (1.0f / 6.0f);
        float B1 = (0.5f * u - 1.0f) * u * u + (2.0f / 3.0f);   // 0.5u^3 - u^2 + 2/3
        float B2 = 1.0f - B0 - B1 - B3;                // partition of unity
        int o = m - 3;                                  // 0..4: first nonzero basis index

        uint32_t hB01, hB23, hB_0, hB12, hB3_;
        {
            __half2 v;
            v = __floats2half2_rn(B0, B1);   hB01 = *reinterpret_cast<uint32_t*>(&v);
            v = __floats2half2_rn(B2, B3);   hB23 = *reinterpret_cast<uint32_t*>(&v);
            v = __floats2half2_rn(0.0f, B0); hB_0 = *reinterpret_cast<uint32_t*>(&v);
            v = __floats2half2_rn(B1, B2);   hB12 = *reinterpret_cast<uint32_t*>(&v);
            v = __floats2half2_rn(B3, 0.0f); hB3_ = *reinterpret_cast<uint32_t*>(&v);
        }
        uint4 out4;
        switch (o) {
            case 0:  out4 = make_uint4(hB01, hB23, 0u, 0u);   break;
            case 1:  out4 = make_uint4(hB_0, hB12, hB3_, 0u); break;
            case 2:  out4 = make_uint4(0u, hB01, hB23, 0u);   break;
            case 3:  out4 = make_uint4(0u, hB_0, hB12, hB3_); break;
            default: out4 = make_uint4(0u, 0u, hB01, hB23);   break;  // o==4
        }

        int mt = b >> 7, row = b & 127;
        char* abase = (char*)g_A;
        {
            int kt = i >> 3;
            size_t tile = ((size_t)(mt * NKT + kt)) * A_TILE_B;
            uint32_t off = (uint32_t)(row * 128 + (i & 7) * 16);
            *reinterpret_cast<uint4*>(abase + tile + swz(off)) = out4;
        }
        {
            float sl = __fdividef(xv, 1.0f + __expf(-xv));
            int kt = 128 + (i >> 6);
            size_t tile = ((size_t)(mt * NKT + kt)) * A_TILE_B;
            uint32_t off = (uint32_t)(row * 128 + (i & 63) * 2);
            *reinterpret_cast<__half*>(abase + tile + swz(off)) = __float2half_rn(sl);
        }
    } else {
        // ----- part B: one group of 8 K-floats per thread -----
        int idx = (blockIdx.x - BLOCKS_A) * 256 + threadIdx.x;
        int o  = idx / (KTOT / 8);
        int kq = idx % (KTOT / 8);
        int k  = kq * 8;
        float4 v0, v1;
        if (k < KSP) {
            const float4* p = reinterpret_cast<const float4*>(spw + (size_t)o * KSP + k);
            v0 = p[0]; v1 = p[1];
        } else {
            const float4* p = reinterpret_cast<const float4*>(baw + (size_t)o * INF + (k - KSP));
            v0 = p[0]; v1 = p[1];
        }
        __half hv[8];
        hv[0] = __float2half_rn(v0.x); hv[1] = __float2half_rn(v0.y);
        hv[2] = __float2half_rn(v0.z); hv[3] = __float2half_rn(v0.w);
        hv[4] = __float2half_rn(v1.x); hv[5] = __float2half_rn(v1.y);
        hv[6] = __float2half_rn(v1.z); hv[7] = __float2half_rn(v1.w);

        int nt = o >> 8, row = o & 255;   // TN=256 tiles
        int kt = k >> 6;
        size_t tile = ((size_t)(nt * NKT + kt)) * B_TILE_B;
        uint32_t off = (uint32_t)(row * 128 + (k & 63) * 2);
        *reinterpret_cast<uint4*>((char*)g_B + tile + swz(off)) = *reinterpret_cast<uint4*>(hv);
    }
}

// ---------------- GEMM: mma.sync fp16, 128x256, dedicated producer warp ----------------
// Warp 8 (lane 0) runs the whole TMA pipeline: empty-wait -> expect_tx -> bulk x2,
// self-throttled by the 4-deep stage ring. Consumer warps 0-7 never touch TMA
// chores; cross-ktile fragment prefetch hides the full-wait seam.
__global__ void __launch_bounds__(NTHREADS, 1) kan_gemm(float* __restrict__ out) {
    extern __shared__ __align__(16) char smem_raw[];
    uint32_t sb = (s2u(smem_raw) + 1023u) & ~1023u;
    int tid = threadIdx.x, wid = tid >> 5, lane = tid & 31;

    if (tid == 0) {
        for (int s = 0; s < STAGES; s++) {
            mbar_init(sb + SOFF_FULL  + 8 * s, 1);     // tx-gated fill
            mbar_init(sb + SOFF_EMPTY + 8 * s, 256);   // consumer arrivals
        }
    }
    __syncthreads();

    int mt = blockIdx.x, nt = blockIdx.y;
    const char* agl = (const char*)g_A + (size_t)mt * NKT * A_TILE_B;
    const char* bgl = (const char*)g_B + (size_t)nt * NKT * B_TILE_B;

    if (wid == 8) {
        // ================= PRODUCER WARP =================
        if (lane == 0) {
            int ephase = 0;
#pragma unroll 1
            for (int j = 0; j < NKT; j++) {
                int sp = j & (STAGES - 1);
                if (j >= STAGES) {
                    mbar_wait(sb + SOFF_EMPTY + 8 * sp, ephase);
                    if (sp == STAGES - 1) ephase ^= 1;
                }
                uint32_t full = sb + SOFF_FULL + 8 * sp;
                mbar_expect_tx(full, STAGE_B);
                uint32_t sa = sb + SOFF_STAGE + sp * STAGE_B;
                bulk_g2s(sa,            agl + (size_t)j * A_TILE_B, A_TILE_B, full);
                bulk_g2s(sa + A_TILE_B, bgl + (size_t)j * B_TILE_B, B_TILE_B, full);
            }
        }
        return;
    }

    // ================= CONSUMER WARPS 0-7 =================
    int warp_m = wid >> 2, warp_n = wid & 3;   // 2 x 4 warp grid, 64x64 per warp

    // ---- per-thread ldmatrix addressing (swizzle-folded) ----
    int g = lane >> 3, r = lane & 7;
    int rA = warp_m * 64 + (g & 1) * 8 + r;
    uint32_t acol0 = (uint32_t)((g >> 1) * 16);
    uint32_t amask = (uint32_t)((rA & 7) << 4);
    int rB = warp_n * 64 + ((g >> 1) & 1) * 8 + r;
    uint32_t bcol0 = (uint32_t)((g & 1) * 16);
    uint32_t bmask = (uint32_t)((rB & 7) << 4);
    uint32_t acol[4], bcol[4];
#pragma unroll
    for (int ks = 0; ks < 4; ks++) {
        acol[ks] = (acol0 + ks * 32) ^ amask;
        bcol[ks] = (bcol0 + ks * 32) ^ bmask;
    }
    uint32_t aRowOff = (uint32_t)(rA * 128);
    uint32_t bRowOff = (uint32_t)(A_TILE_B + rB * 128);

    float acc[4][8][4];
#pragma unroll
    for (int mi = 0; mi < 4; mi++)
#pragma unroll
        for (int nj = 0; nj < 8; nj++)
#pragma unroll
            for (int q = 0; q < 4; q++) acc[mi][nj][q] = 0.0f;

    // ---- pipeline prologue: wait stage 0, load its ks=0 fragments ----
    uint32_t af[2][4][4], bf[2][4][4];
    mbar_wait(sb + SOFF_FULL + 0, 0);
    {
        uint32_t baseA = sb + SOFF_STAGE + aRowOff;
        uint32_t baseB = sb + SOFF_STAGE + bRowOff;
#pragma unroll
        for (int mi = 0; mi < 4; mi++) ldsm4(af[0][mi], baseA + mi * 2048 + acol[0]);
#pragma unroll
        for (int np = 0; np < 4; np++) ldsm4(bf[0][np], baseB + np * 2048 + bcol[0]);
    }

#pragma unroll 1
    for (int kt = 0; kt < NKT; kt++) {
        int s = kt & (STAGES - 1);
        uint32_t sbase = sb + SOFF_STAGE + s * STAGE_B;
        uint32_t baseA = sbase + aRowOff;
        uint32_t baseB = sbase + bRowOff;

#pragma unroll
        for (int ks = 0; ks < 4; ks++) {
            int cur = ks & 1, nxt = cur ^ 1;
            if (ks < 3) {
#pragma unroll
                for (int mi = 0; mi < 4; mi++) ldsm4(af[nxt][mi], baseA + mi * 2048 + acol[ks + 1]);
#pragma unroll
                for (int np = 0; np < 4; np++) ldsm4(bf[nxt][np], baseB + np * 2048 + bcol[ks + 1]);
                // all of this thread's LDSMs from stage s are done
                if (ks == 2) mbar_arrive(sb + SOFF_EMPTY + 8 * s);
            } else if (kt + 1 < NKT) {
                // cross-tile: wait next stage + prefetch its ks=0 fragments
                int kn = kt + 1;
                int s2 = kn & (STAGES - 1);
                mbar_wait(sb + SOFF_FULL + 8 * s2, (kn >> 2) & 1);
                uint32_t nbase = sb + SOFF_STAGE + s2 * STAGE_B;
#pragma unroll
                for (int mi = 0; mi < 4; mi++) ldsm4(af[nxt][mi], nbase + aRowOff + mi * 2048 + acol[0]);
#pragma unroll
                for (int np = 0; np < 4; np++) ldsm4(bf[nxt][np], nbase + bRowOff + np * 2048 + bcol[0]);
            }
#pragma unroll
            for (int mi = 0; mi < 4; mi++)
#pragma unroll
                for (int nj = 0; nj < 8; nj++)
                    mma_f16(acc[mi][nj], af[cur][mi],
                            bf[cur][nj >> 1][(nj & 1) * 2], bf[cur][nj >> 1][(nj & 1) * 2 + 1]);
        }
    }

    // ---- epilogue: FP32 accumulators -> global ----
    int row0 = mt * 128 + warp_m * 64 + (lane >> 2);
    int col0 = nt * 256 + warp_n * 64 + (lane & 3) * 2;
#pragma unroll
    for (int mi = 0; mi < 4; mi++) {
#pragma unroll
        for (int nj = 0; nj < 8; nj++) {
            float* p0 = out + (size_t)(row0 + mi * 16) * OUTF + col0 + nj * 8;
            float* p1 = out + (size_t)(row0 + mi * 16 + 8) * OUTF + col0 + nj * 8;
            *reinterpret_cast<float2*>(p0) = make_float2(acc[mi][nj][0], acc[mi][nj][1]);
            *reinterpret_cast<float2*>(p1) = make_float2(acc[mi][nj][2], acc[mi][nj][3]);
        }
    }
}

// ---------------- host launch ----------------
extern "C" void kernel_launch(void* const* d_in, const int* in_sizes, int n_in,
                              void* d_out, int out_size) {
    (void)in_sizes; (void)n_in; (void)out_size;
    const float* x   = (const float*)d_in[0];
    const float* spw = (const float*)d_in[1];
    const float* baw = (const float*)d_in[2];
    float* out = (float*)d_out;

    prolog_ab<<<BLOCKS_A + BLOCKS_B, 256>>>(x, spw, baw);

    cudaFuncSetAttribute(kan_gemm, cudaFuncAttributeMaxDynamicSharedMemorySize, SMEM_NEED);
    kan_gemm<<<dim3(MT, NT), NTHREADS, SMEM_NEED>>>(out);
}

// round 13
// speedup vs baseline: 3.1007x; 3.1007x over previous
#include <cuda_runtime.h>
#include <cuda_fp16.h>
#include <cstdint>
#include <cstddef>

#define DI __device__ __forceinline__

// ---------------- problem constants ----------------
constexpr int BATCH = 4096;
constexpr int INF   = 1024;
constexpr int OUTF  = 1024;
constexpr int KSP   = INF * 8;       // 8192 spline K
constexpr int KTOT  = KSP + INF;     // 9216 total K
constexpr int KBLK  = 64;            // fp16 per K-tile -> 128 B rows (SW128)
constexpr int NKT   = KTOT / KBLK;   // 144 K-tiles
constexpr int TM    = 128;
constexpr int TN    = 256;           // proven best: operand reuse beats occupancy
constexpr int MT    = BATCH / TM;    // 32
constexpr int NT    = OUTF / TN;     // 4
constexpr int STAGES = 4;
constexpr int A_TILE_B = TM * KBLK * 2;       // 16384
constexpr int B_TILE_B = TN * KBLK * 2;       // 32768
constexpr int STAGE_B  = A_TILE_B + B_TILE_B; // 49152

constexpr int SOFF_FULL  = 0;    // 4 x 8B
constexpr int SOFF_EMPTY = 32;   // 4 x 8B
constexpr int SOFF_STAGE = 1024;
constexpr int SMEM_NEED  = 1024 + SOFF_STAGE + STAGES * STAGE_B; // 198656 < 227KB cap

constexpr int BLOCKS_A = (BATCH * INF) / 256;       // 16384
constexpr int BLOCKS_B = (OUTF * (KTOT / 8)) / 256; // 4608

// ---------------- scratch (device globals; no allocation) ----------------
__device__ __half g_A[(size_t)MT * NKT * TM * KBLK];  // 75.5 MB tiled+swizzled activations
__device__ __half g_B[(size_t)NT * NKT * TN * KBLK];  // 18.9 MB tiled+swizzled weights

// ---------------- PTX helpers ----------------
DI uint32_t s2u(const void* p) {
    uint32_t a;
    asm("{ .reg .u64 t; cvta.to.shared.u64 t, %1; cvt.u32.u64 %0, t; }" : "=r"(a) : "l"(p));
    return a;
}
DI uint32_t swz(uint32_t off) { return off ^ ((off >> 3) & 0x70); }

DI void mbar_init(uint32_t a, uint32_t cnt) {
    asm volatile("mbarrier.init.shared.b64 [%0], %1;" :: "r"(a), "r"(cnt) : "memory");
}
DI void mbar_arrive(uint32_t a) {
    asm volatile("mbarrier.arrive.release.cta.shared.b64 _, [%0];" :: "r"(a) : "memory");
}
DI void mbar_expect_tx(uint32_t a, uint32_t bytes) {
    asm volatile("mbarrier.arrive.expect_tx.shared.b64 _, [%0], %1;" :: "r"(a), "r"(bytes) : "memory");
}
DI void mbar_wait(uint32_t a, uint32_t parity) {
    asm volatile(
        "{\n\t"
        ".reg .pred P1;\n\t"
        "WAIT_LOOP_%=:\n\t"
        "mbarrier.try_wait.parity.acquire.cta.shared::cta.b64 P1, [%0], %1, 0x989680;\n\t"
        "@P1 bra.uni WAIT_DONE_%=;\n\t"
        "bra.uni WAIT_LOOP_%=;\n\t"
        "WAIT_DONE_%=:\n\t"
        "}"
        :: "r"(a), "r"(parity) : "memory");
}
DI void bulk_g2s(uint32_t dst, const void* src, uint32_t bytes, uint32_t mbar) {
    asm volatile(
        "cp.async.bulk.shared::cluster.global.mbarrier::complete_tx::bytes [%0], [%1], %2, [%3];"
        :: "r"(dst), "l"(src), "r"(bytes), "r"(mbar) : "memory");
}
DI void ldsm4(uint32_t* r, uint32_t addr) {
    asm volatile("ldmatrix.sync.aligned.m8n8.x4.shared.b16 {%0,%1,%2,%3}, [%4];"
                 : "=r"(r[0]), "=r"(r[1]), "=r"(r[2]), "=r"(r[3]) : "r"(addr));
}
DI void mma_f16(float* c, const uint32_t* a, uint32_t b0, uint32_t b1) {
    asm volatile(
        "mma.sync.aligned.m16n8k16.row.col.f32.f16.f16.f32 "
        "{%0,%1,%2,%3}, {%4,%5,%6,%7}, {%8,%9}, {%0,%1,%2,%3};"
        : "+f"(c[0]), "+f"(c[1]), "+f"(c[2]), "+f"(c[3])
        : "r"(a[0]), "r"(a[1]), "r"(a[2]), "r"(a[3]), "r"(b0), "r"(b1));
}

// ---------------- merged prologue: A (closed-form bases + silu) and B ----------------
__global__ void __launch_bounds__(256) prolog_ab(const float* __restrict__ x,
                                                 const float* __restrict__ spw,
                                                 const float* __restrict__ baw) {
    if (blockIdx.x < BLOCKS_A) {
        // ----- part A: one (b, i) per thread -----
        int idx = blockIdx.x * 256 + threadIdx.x;
        int b = idx >> 10;
        int i = idx & 1023;
        float xv = x[idx];

        // tanh(x) = 1 - 2/(e^{2x}+1)
        float t = 1.0f - __fdividef(2.0f, __expf(2.0f * xv) + 1.0f);

        // closed-form cubic B-spline: only 4 nonzero bases
        float sc = (t + 2.2f) * 2.5f;                  // interval coord, in [3, 8]
        int m = __float2int_rd(sc);
        m = max(3, min(7, m));                          // clamp (t = +-1 edges)
        float u = sc - (float)m;                        // [0, 1)
        float omu = 1.0f - u;
        float B0 = omu * omu * omu * (1.0f / 6.0f);
        float B3 = u * u * u * (1.0f / 6.0f);
        float B1 = (0.5f * u - 1.0f) * u * u + (2.0f / 3.0f);   // 0.5u^3 - u^2 + 2/3
        float B2 = 1.0f - B0 - B1 - B3;                // partition of unity
        int o = m - 3;                                  // 0..4: first nonzero basis index

        uint32_t hB01, hB23, hB_0, hB12, hB3_;
        {
            __half2 v;
            v = __floats2half2_rn(B0, B1);   hB01 = *reinterpret_cast<uint32_t*>(&v);
            v = __floats2half2_rn(B2, B3);   hB23 = *reinterpret_cast<uint32_t*>(&v);
            v = __floats2half2_rn(0.0f, B0); hB_0 = *reinterpret_cast<uint32_t*>(&v);
            v = __floats2half2_rn(B1, B2);   hB12 = *reinterpret_cast<uint32_t*>(&v);
            v = __floats2half2_rn(B3, 0.0f); hB3_ = *reinterpret_cast<uint32_t*>(&v);
        }
        uint4 out4;
        switch (o) {
            case 0:  out4 = make_uint4(hB01, hB23, 0u, 0u);   break;
            case 1:  out4 = make_uint4(hB_0, hB12, hB3_, 0u); break;
            case 2:  out4 = make_uint4(0u, hB01, hB23, 0u);   break;
            case 3:  out4 = make_uint4(0u, hB_0, hB12, hB3_); break;
            default: out4 = make_uint4(0u, 0u, hB01, hB23);   break;  // o==4
        }

        int mt = b >> 7, row = b & 127;
        char* abase = (char*)g_A;
        {
            int kt = i >> 3;
            size_t tile = ((size_t)(mt * NKT + kt)) * A_TILE_B;
            uint32_t off = (uint32_t)(row * 128 + (i & 7) * 16);
            *reinterpret_cast<uint4*>(abase + tile + swz(off)) = out4;
        }
        {
            float sl = __fdividef(xv, 1.0f + __expf(-xv));
            int kt = 128 + (i >> 6);
            size_t tile = ((size_t)(mt * NKT + kt)) * A_TILE_B;
            uint32_t off = (uint32_t)(row * 128 + (i & 63) * 2);
            *reinterpret_cast<__half*>(abase + tile + swz(off)) = __float2half_rn(sl);
        }
    } else {
        // ----- part B: one group of 8 K-floats per thread -----
        int idx = (blockIdx.x - BLOCKS_A) * 256 + threadIdx.x;
        int o  = idx / (KTOT / 8);
        int kq = idx % (KTOT / 8);
        int k  = kq * 8;
        float4 v0, v1;
        if (k < KSP) {
            const float4* p = reinterpret_cast<const float4*>(spw + (size_t)o * KSP + k);
            v0 = p[0]; v1 = p[1];
        } else {
            const float4* p = reinterpret_cast<const float4*>(baw + (size_t)o * INF + (k - KSP));
            v0 = p[0]; v1 = p[1];
        }
        __half hv[8];
        hv[0] = __float2half_rn(v0.x); hv[1] = __float2half_rn(v0.y);
        hv[2] = __float2half_rn(v0.z); hv[3] = __float2half_rn(v0.w);
        hv[4] = __float2half_rn(v1.x); hv[5] = __float2half_rn(v1.y);
        hv[6] = __float2half_rn(v1.z); hv[7] = __float2half_rn(v1.w);

        int nt = o >> 8, row = o & 255;   // TN=256 tiles
        int kt = k >> 6;
        size_t tile = ((size_t)(nt * NKT + kt)) * B_TILE_B;
        uint32_t off = (uint32_t)(row * 128 + (k & 63) * 2);
        *reinterpret_cast<uint4*>((char*)g_B + tile + swz(off)) = *reinterpret_cast<uint4*>(hv);
    }
}

// ---------------- GEMM: mma.sync fp16, 128x256, rotating producer warp ----------------
// TMA chores for tile j = kt+3 are issued by lane 0 of warp (kt & 7): each warp
// pays the chore cost once per 8 tiles instead of warp 0 paying it every tile.
// Empty-barrier parity is closed-form in j since the issuer rotates.
__global__ void __launch_bounds__(256, 1) kan_gemm(float* __restrict__ out) {
    extern __shared__ __align__(16) char smem_raw[];
    uint32_t sb = (s2u(smem_raw) + 1023u) & ~1023u;
    int tid = threadIdx.x, wid = tid >> 5, lane = tid & 31;
    int warp_m = wid >> 2, warp_n = wid & 3;   // 2 x 4 warp grid, 64x64 per warp

    if (tid == 0) {
        for (int s = 0; s < STAGES; s++) {
            mbar_init(sb + SOFF_FULL  + 8 * s, 1);     // tx-gated fill
            mbar_init(sb + SOFF_EMPTY + 8 * s, 256);   // consumer arrivals
        }
    }
    __syncthreads();

    int mt = blockIdx.x, nt = blockIdx.y;
    const char* agl = (const char*)g_A + (size_t)mt * NKT * A_TILE_B;
    const char* bgl = (const char*)g_B + (size_t)nt * NKT * B_TILE_B;

    // ---- per-thread ldmatrix addressing (swizzle-folded) ----
    int g = lane >> 3, r = lane & 7;
    int rA = warp_m * 64 + (g & 1) * 8 + r;
    uint32_t acol0 = (uint32_t)((g >> 1) * 16);
    uint32_t amask = (uint32_t)((rA & 7) << 4);
    int rB = warp_n * 64 + ((g >> 1) & 1) * 8 + r;
    uint32_t bcol0 = (uint32_t)((g & 1) * 16);
    uint32_t bmask = (uint32_t)((rB & 7) << 4);
    uint32_t acol[4], bcol[4];
#pragma unroll
    for (int ks = 0; ks < 4; ks++) {
        acol[ks] = (acol0 + ks * 32) ^ amask;
        bcol[ks] = (bcol0 + ks * 32) ^ bmask;
    }
    uint32_t aRowOff = (uint32_t)(rA * 128);
    uint32_t bRowOff = (uint32_t)(A_TILE_B + rB * 128);

    float acc[4][8][4];
#pragma unroll
    for (int mi = 0; mi < 4; mi++)
#pragma unroll
        for (int nj = 0; nj < 8; nj++)
#pragma unroll
            for (int q = 0; q < 4; q++) acc[mi][nj][q] = 0.0f;

    // ---- prefetch first STAGES-1 tiles (warp 0 lane 0; no prior waits needed) ----
    if (tid == 0) {
#pragma unroll
        for (int p = 0; p < STAGES - 1; p++) {
            uint32_t full = sb + SOFF_FULL + 8 * p;
            mbar_expect_tx(full, STAGE_B);
            uint32_t sa = sb + SOFF_STAGE + p * STAGE_B;
            bulk_g2s(sa,            agl + (size_t)p * A_TILE_B, A_TILE_B, full);
            bulk_g2s(sa + A_TILE_B, bgl + (size_t)p * B_TILE_B, B_TILE_B, full);
        }
    }

    // ---- pipeline prologue: wait stage 0, load its ks=0 fragments ----
    uint32_t af[2][4][4], bf[2][4][4];
    mbar_wait(sb + SOFF_FULL + 0, 0);
    {
        uint32_t baseA = sb + SOFF_STAGE + aRowOff;
        uint32_t baseB = sb + SOFF_STAGE + bRowOff;
#pragma unroll
        for (int mi = 0; mi < 4; mi++) ldsm4(af[0][mi], baseA + mi * 2048 + acol[0]);
#pragma unroll
        for (int np = 0; np < 4; np++) ldsm4(bf[0][np], baseB + np * 2048 + bcol[0]);
    }

#pragma unroll 1
    for (int kt = 0; kt < NKT; kt++) {
        // ---- rotating producer: warp (kt & 7), lane 0 handles tile kt+3 ----
        if (wid == (kt & 7) && lane == 0) {
            int j = kt + STAGES - 1;
            if (j < NKT) {
                int sp = j & (STAGES - 1);
                if (j >= STAGES) {
                    // parity of empty[sp] for the (j>>2)-th occupancy
                    mbar_wait(sb + SOFF_EMPTY + 8 * sp, ((j >> 2) & 1) ^ 1);
                }
                uint32_t full = sb + SOFF_FULL + 8 * sp;
                mbar_expect_tx(full, STAGE_B);
                uint32_t sa = sb + SOFF_STAGE + sp * STAGE_B;
                bulk_g2s(sa,            agl + (size_t)j * A_TILE_B, A_TILE_B, full);
                bulk_g2s(sa + A_TILE_B, bgl + (size_t)j * B_TILE_B, B_TILE_B, full);
            }
        }
        int s = kt & (STAGES - 1);
        uint32_t sbase = sb + SOFF_STAGE + s * STAGE_B;
        uint32_t baseA = sbase + aRowOff;
        uint32_t baseB = sbase + bRowOff;

#pragma unroll
        for (int ks = 0; ks < 4; ks++) {
            int cur = ks & 1, nxt = cur ^ 1;
            if (ks < 3) {
#pragma unroll
                for (int mi = 0; mi < 4; mi++) ldsm4(af[nxt][mi], baseA + mi * 2048 + acol[ks + 1]);
#pragma unroll
                for (int np = 0; np < 4; np++) ldsm4(bf[nxt][np], baseB + np * 2048 + bcol[ks + 1]);
                // all of this thread's LDSMs from stage s are done
                if (ks == 2) mbar_arrive(sb + SOFF_EMPTY + 8 * s);
            } else if (kt + 1 < NKT) {
                // cross-tile: wait next stage + prefetch its ks=0 fragments
                int kn = kt + 1;
                int s2 = kn & (STAGES - 1);
                mbar_wait(sb + SOFF_FULL + 8 * s2, (kn >> 2) & 1);
                uint32_t nbase = sb + SOFF_STAGE + s2 * STAGE_B;
#pragma unroll
                for (int mi = 0; mi < 4; mi++) ldsm4(af[nxt][mi], nbase + aRowOff + mi * 2048 + acol[0]);
#pragma unroll
                for (int np = 0; np < 4; np++) ldsm4(bf[nxt][np], nbase + bRowOff + np * 2048 + bcol[0]);
            }
#pragma unroll
            for (int mi = 0; mi < 4; mi++)
#pragma unroll
                for (int nj = 0; nj < 8; nj++)
                    mma_f16(acc[mi][nj], af[cur][mi],
                            bf[cur][nj >> 1][(nj & 1) * 2], bf[cur][nj >> 1][(nj & 1) * 2 + 1]);
        }
    }

    // ---- epilogue: FP32 accumulators -> global ----
    int row0 = mt * 128 + warp_m * 64 + (lane >> 2);
    int col0 = nt * 256 + warp_n * 64 + (lane & 3) * 2;
#pragma unroll
    for (int mi = 0; mi < 4; mi++) {
#pragma unroll
        for (int nj = 0; nj < 8; nj++) {
            float* p0 = out + (size_t)(row0 + mi * 16) * OUTF + col0 + nj * 8;
            float* p1 = out + (size_t)(row0 + mi * 16 + 8) * OUTF + col0 + nj * 8;
            *reinterpret_cast<float2*>(p0) = make_float2(acc[mi][nj][0], acc[mi][nj][1]);
            *reinterpret_cast<float2*>(p1) = make_float2(acc[mi][nj][2], acc[mi][nj][3]);
        }
    }
}

// ---------------- host launch ----------------
extern "C" void kernel_launch(void* const* d_in, const int* in_sizes, int n_in,
                              void* d_out, int out_size) {
    (void)in_sizes; (void)n_in; (void)out_size;
    const float* x   = (const float*)d_in[0];
    const float* spw = (const float*)d_in[1];
    const float* baw = (const float*)d_in[2];
    float* out = (float*)d_out;

    prolog_ab<<<BLOCKS_A + BLOCKS_B, 256>>>(x, spw, baw);

    cudaFuncSetAttribute(kan_gemm, cudaFuncAttributeMaxDynamicSharedMemorySize, SMEM_NEED);
    kan_gemm<<<dim3(MT, NT), 256, SMEM_NEED>>>(out);
}

// round 14
// speedup vs baseline: 3.1012x; 1.0002x over previous
#include <cuda_runtime.h>
#include <cuda_fp16.h>
#include <cstdint>
#include <cstddef>

#define DI __device__ __forceinline__

// ---------------- problem constants ----------------
constexpr int BATCH = 4096;
constexpr int INF   = 1024;
constexpr int OUTF  = 1024;
constexpr int KSP   = INF * 8;       // 8192 spline K
constexpr int KTOT  = KSP + INF;     // 9216 total K
constexpr int KBLK  = 64;            // fp16 per K-tile -> 128 B rows (SW128)
constexpr int NKT   = KTOT / KBLK;   // 144 K-tiles
constexpr int TM    = 128;
constexpr int TN    = 256;           // proven best: operand reuse beats occupancy
constexpr int MT    = BATCH / TM;    // 32
constexpr int NT    = OUTF / TN;     // 4
constexpr int STAGES = 4;
constexpr int A_TILE_B = TM * KBLK * 2;       // 16384
constexpr int B_TILE_B = TN * KBLK * 2;       // 32768
constexpr int STAGE_B  = A_TILE_B + B_TILE_B; // 49152

constexpr int SOFF_FULL  = 0;    // 4 x 8B
constexpr int SOFF_EMPTY = 32;   // 4 x 8B
constexpr int SOFF_STAGE = 1024;
constexpr int SMEM_NEED  = 1024 + SOFF_STAGE + STAGES * STAGE_B; // 198656 < 227KB cap

constexpr int BLOCKS_A = (BATCH * INF) / 256;       // 16384
constexpr int BLOCKS_B = (OUTF * (KTOT / 8)) / 256; // 4608

// ---------------- scratch (device globals; no allocation) ----------------
__device__ __half g_A[(size_t)MT * NKT * TM * KBLK];  // 75.5 MB tiled+swizzled activations
__device__ __half g_B[(size_t)NT * NKT * TN * KBLK];  // 18.9 MB tiled+swizzled weights

// ---------------- PTX helpers ----------------
DI uint32_t s2u(const void* p) {
    uint32_t a;
    asm("{ .reg .u64 t; cvta.to.shared.u64 t, %1; cvt.u32.u64 %0, t; }" : "=r"(a) : "l"(p));
    return a;
}
DI uint32_t swz(uint32_t off) { return off ^ ((off >> 3) & 0x70); }

DI void mbar_init(uint32_t a, uint32_t cnt) {
    asm volatile("mbarrier.init.shared.b64 [%0], %1;" :: "r"(a), "r"(cnt) : "memory");
}
DI void mbar_arrive(uint32_t a) {
    asm volatile("mbarrier.arrive.release.cta.shared.b64 _, [%0];" :: "r"(a) : "memory");
}
DI void mbar_expect_tx(uint32_t a, uint32_t bytes) {
    asm volatile("mbarrier.arrive.expect_tx.shared.b64 _, [%0], %1;" :: "r"(a), "r"(bytes) : "memory");
}
DI void mbar_wait(uint32_t a, uint32_t parity) {
    asm volatile(
        "{\n\t"
        ".reg .pred P1;\n\t"
        "WAIT_LOOP_%=:\n\t"
        "mbarrier.try_wait.parity.acquire.cta.shared::cta.b64 P1, [%0], %1, 0x989680;\n\t"
        "@P1 bra.uni WAIT_DONE_%=;\n\t"
        "bra.uni WAIT_LOOP_%=;\n\t"
        "WAIT_DONE_%=:\n\t"
        "}"
        :: "r"(a), "r"(parity) : "memory");
}
DI void bulk_g2s(uint32_t dst, const void* src, uint32_t bytes, uint32_t mbar) {
    asm volatile(
        "cp.async.bulk.shared::cluster.global.mbarrier::complete_tx::bytes [%0], [%1], %2, [%3];"
        :: "r"(dst), "l"(src), "r"(bytes), "r"(mbar) : "memory");
}
DI void ldsm4(uint32_t* r, uint32_t addr) {
    asm volatile("ldmatrix.sync.aligned.m8n8.x4.shared.b16 {%0,%1,%2,%3}, [%4];"
                 : "=r"(r[0]), "=r"(r[1]), "=r"(r[2]), "=r"(r[3]) : "r"(addr));
}
DI void mma_f16(float* c, const uint32_t* a, uint32_t b0, uint32_t b1) {
    asm volatile(
        "mma.sync.aligned.m16n8k16.row.col.f32.f16.f16.f32 "
        "{%0,%1,%2,%3}, {%4,%5,%6,%7}, {%8,%9}, {%0,%1,%2,%3};"
        : "+f"(c[0]), "+f"(c[1]), "+f"(c[2]), "+f"(c[3])
        : "r"(a[0]), "r"(a[1]), "r"(a[2]), "r"(a[3]), "r"(b0), "r"(b1));
}

// ---------------- merged prologue: A (closed-form bases + silu) and B ----------------
__global__ void __launch_bounds__(256) prolog_ab(const float* __restrict__ x,
                                                 const float* __restrict__ spw,
                                                 const float* __restrict__ baw) {
    if (blockIdx.x < BLOCKS_A) {
        // ----- part A: one (b, i) per thread -----
        int idx = blockIdx.x * 256 + threadIdx.x;
        int b = idx >> 10;
        int i = idx & 1023;
        float xv = x[idx];

        // tanh(x) = 1 - 2/(e^{2x}+1)
        float t = 1.0f - __fdividef(2.0f, __expf(2.0f * xv) + 1.0f);

        // closed-form cubic B-spline: only 4 nonzero bases
        float sc = (t + 2.2f) * 2.5f;                  // interval coord, in [3, 8]
        int m = __float2int_rd(sc);
        m = max(3, min(7, m));                          // clamp (t = +-1 edges)
        float u = sc - (float)m;                        // [0, 1)
        float omu = 1.0f - u;
        float B0 = omu * omu * omu * (1.0f / 6.0f);
        float B3 = u * u * u * (1.0f / 6.0f);
        float B1 = (0.5f * u - 1.0f) * u * u + (2.0f / 3.0f);   // 0.5u^3 - u^2 + 2/3
        float B2 = 1.0f - B0 - B1 - B3;                // partition of unity
        int o = m - 3;                                  // 0..4: first nonzero basis index

        uint32_t hB01, hB23, hB_0, hB12, hB3_;
        {
            __half2 v;
            v = __floats2half2_rn(B0, B1);   hB01 = *reinterpret_cast<uint32_t*>(&v);
            v = __floats2half2_rn(B2, B3);   hB23 = *reinterpret_cast<uint32_t*>(&v);
            v = __floats2half2_rn(0.0f, B0); hB_0 = *reinterpret_cast<uint32_t*>(&v);
            v = __floats2half2_rn(B1, B2);   hB12 = *reinterpret_cast<uint32_t*>(&v);
            v = __floats2half2_rn(B3, 0.0f); hB3_ = *reinterpret_cast<uint32_t*>(&v);
        }
        uint4 out4;
        switch (o) {
            case 0:  out4 = make_uint4(hB01, hB23, 0u, 0u);   break;
            case 1:  out4 = make_uint4(hB_0, hB12, hB3_, 0u); break;
            case 2:  out4 = make_uint4(0u, hB01, hB23, 0u);   break;
            case 3:  out4 = make_uint4(0u, hB_0, hB12, hB3_); break;
            default: out4 = make_uint4(0u, 0u, hB01, hB23);   break;  // o==4
        }

        int mt = b >> 7, row = b & 127;
        char* abase = (char*)g_A;
        {
            int kt = i >> 3;
            size_t tile = ((size_t)(mt * NKT + kt)) * A_TILE_B;
            uint32_t off = (uint32_t)(row * 128 + (i & 7) * 16);
            *reinterpret_cast<uint4*>(abase + tile + swz(off)) = out4;
        }
        {
            float sl = __fdividef(xv, 1.0f + __expf(-xv));
            int kt = 128 + (i >> 6);
            size_t tile = ((size_t)(mt * NKT + kt)) * A_TILE_B;
            uint32_t off = (uint32_t)(row * 128 + (i & 63) * 2);
            *reinterpret_cast<__half*>(abase + tile + swz(off)) = __float2half_rn(sl);
        }
    } else {
        // ----- part B: one group of 8 K-floats per thread -----
        int idx = (blockIdx.x - BLOCKS_A) * 256 + threadIdx.x;
        int o  = idx / (KTOT / 8);
        int kq = idx % (KTOT / 8);
        int k  = kq * 8;
        float4 v0, v1;
        if (k < KSP) {
            const float4* p = reinterpret_cast<const float4*>(spw + (size_t)o * KSP + k);
            v0 = p[0]; v1 = p[1];
        } else {
            const float4* p = reinterpret_cast<const float4*>(baw + (size_t)o * INF + (k - KSP));
            v0 = p[0]; v1 = p[1];
        }
        __half hv[8];
        hv[0] = __float2half_rn(v0.x); hv[1] = __float2half_rn(v0.y);
        hv[2] = __float2half_rn(v0.z); hv[3] = __float2half_rn(v0.w);
        hv[4] = __float2half_rn(v1.x); hv[5] = __float2half_rn(v1.y);
        hv[6] = __float2half_rn(v1.z); hv[7] = __float2half_rn(v1.w);

        int nt = o >> 8, row = o & 255;   // TN=256 tiles
        int kt = k >> 6;
        size_t tile = ((size_t)(nt * NKT + kt)) * B_TILE_B;
        uint32_t off = (uint32_t)(row * 128 + (k & 63) * 2);
        *reinterpret_cast<uint4*>((char*)g_B + tile + swz(off)) = *reinterpret_cast<uint4*>(hv);
    }
}

// ---------------- GEMM: mma.sync fp16, 128x256, rotating producer warp ----------------
// Per-warp elected empty-arrive: ldmatrix is warp-collective, so lane 0 finishing
// its stage-s LDSMs implies the whole warp is done; empty[] counts 8 (one/warp).
__global__ void __launch_bounds__(256, 1) kan_gemm(float* __restrict__ out) {
    extern __shared__ __align__(16) char smem_raw[];
    uint32_t sb = (s2u(smem_raw) + 1023u) & ~1023u;
    int tid = threadIdx.x, wid = tid >> 5, lane = tid & 31;
    int warp_m = wid >> 2, warp_n = wid & 3;   // 2 x 4 warp grid, 64x64 per warp

    if (tid == 0) {
        for (int s = 0; s < STAGES; s++) {
            mbar_init(sb + SOFF_FULL  + 8 * s, 1);   // tx-gated fill
            mbar_init(sb + SOFF_EMPTY + 8 * s, 8);   // one elected arrive per warp
        }
    }
    __syncthreads();

    int mt = blockIdx.x, nt = blockIdx.y;
    const char* agl = (const char*)g_A + (size_t)mt * NKT * A_TILE_B;
    const char* bgl = (const char*)g_B + (size_t)nt * NKT * B_TILE_B;

    // ---- per-thread ldmatrix addressing (swizzle-folded) ----
    int g = lane >> 3, r = lane & 7;
    int rA = warp_m * 64 + (g & 1) * 8 + r;
    uint32_t acol0 = (uint32_t)((g >> 1) * 16);
    uint32_t amask = (uint32_t)((rA & 7) << 4);
    int rB = warp_n * 64 + ((g >> 1) & 1) * 8 + r;
    uint32_t bcol0 = (uint32_t)((g & 1) * 16);
    uint32_t bmask = (uint32_t)((rB & 7) << 4);
    uint32_t acol[4], bcol[4];
#pragma unroll
    for (int ks = 0; ks < 4; ks++) {
        acol[ks] = (acol0 + ks * 32) ^ amask;
        bcol[ks] = (bcol0 + ks * 32) ^ bmask;
    }
    uint32_t aRowOff = (uint32_t)(rA * 128);
    uint32_t bRowOff = (uint32_t)(A_TILE_B + rB * 128);

    float acc[4][8][4];
#pragma unroll
    for (int mi = 0; mi < 4; mi++)
#pragma unroll
        for (int nj = 0; nj < 8; nj++)
#pragma unroll
            for (int q = 0; q < 4; q++) acc[mi][nj][q] = 0.0f;

    // ---- prefetch first STAGES-1 tiles (warp 0 lane 0; no prior waits needed) ----
    if (tid == 0) {
#pragma unroll
        for (int p = 0; p < STAGES - 1; p++) {
            uint32_t full = sb + SOFF_FULL + 8 * p;
            mbar_expect_tx(full, STAGE_B);
            uint32_t sa = sb + SOFF_STAGE + p * STAGE_B;
            bulk_g2s(sa,            agl + (size_t)p * A_TILE_B, A_TILE_B, full);
            bulk_g2s(sa + A_TILE_B, bgl + (size_t)p * B_TILE_B, B_TILE_B, full);
        }
    }

    // ---- pipeline prologue: wait stage 0, load its ks=0 fragments ----
    uint32_t af[2][4][4], bf[2][4][4];
    mbar_wait(sb + SOFF_FULL + 0, 0);
    {
        uint32_t baseA = sb + SOFF_STAGE + aRowOff;
        uint32_t baseB = sb + SOFF_STAGE + bRowOff;
#pragma unroll
        for (int mi = 0; mi < 4; mi++) ldsm4(af[0][mi], baseA + mi * 2048 + acol[0]);
#pragma unroll
        for (int np = 0; np < 4; np++) ldsm4(bf[0][np], baseB + np * 2048 + bcol[0]);
    }

#pragma unroll 1
    for (int kt = 0; kt < NKT; kt++) {
        // ---- rotating producer: warp (kt & 7), lane 0 handles tile kt+3 ----
        if (wid == (kt & 7) && lane == 0) {
            int j = kt + STAGES - 1;
            if (j < NKT) {
                int sp = j & (STAGES - 1);
                if (j >= STAGES) {
                    // parity of empty[sp] for the (j>>2)-th occupancy
                    mbar_wait(sb + SOFF_EMPTY + 8 * sp, ((j >> 2) & 1) ^ 1);
                }
                uint32_t full = sb + SOFF_FULL + 8 * sp;
                mbar_expect_tx(full, STAGE_B);
                uint32_t sa = sb + SOFF_STAGE + sp * STAGE_B;
                bulk_g2s(sa,            agl + (size_t)j * A_TILE_B, A_TILE_B, full);
                bulk_g2s(sa + A_TILE_B, bgl + (size_t)j * B_TILE_B, B_TILE_B, full);
            }
        }
        int s = kt & (STAGES - 1);
        uint32_t sbase = sb + SOFF_STAGE + s * STAGE_B;
        uint32_t baseA = sbase + aRowOff;
        uint32_t baseB = sbase + bRowOff;

#pragma unroll
        for (int ks = 0; ks < 4; ks++) {
            int cur = ks & 1, nxt = cur ^ 1;
            if (ks < 3) {
#pragma unroll
                for (int mi = 0; mi < 4; mi++) ldsm4(af[nxt][mi], baseA + mi * 2048 + acol[ks + 1]);
#pragma unroll
                for (int np = 0; np < 4; np++) ldsm4(bf[nxt][np], baseB + np * 2048 + bcol[ks + 1]);
                // warp's stage-s LDSMs all complete here (ldmatrix is warp-collective)
                if (ks == 2 && lane == 0) mbar_arrive(sb + SOFF_EMPTY + 8 * s);
            } else if (kt + 1 < NKT) {
                // cross-tile: wait next stage + prefetch its ks=0 fragments
                int kn = kt + 1;
                int s2 = kn & (STAGES - 1);
                mbar_wait(sb + SOFF_FULL + 8 * s2, (kn >> 2) & 1);
                uint32_t nbase = sb + SOFF_STAGE + s2 * STAGE_B;
#pragma unroll
                for (int mi = 0; mi < 4; mi++) ldsm4(af[nxt][mi], nbase + aRowOff + mi * 2048 + acol[0]);
#pragma unroll
                for (int np = 0; np < 4; np++) ldsm4(bf[nxt][np], nbase + bRowOff + np * 2048 + bcol[0]);
            }
#pragma unroll
            for (int mi = 0; mi < 4; mi++)
#pragma unroll
                for (int nj = 0; nj < 8; nj++)
                    mma_f16(acc[mi][nj], af[cur][mi],
                            bf[cur][nj >> 1][(nj & 1) * 2], bf[cur][nj >> 1][(nj & 1) * 2 + 1]);
        }
    }

    // ---- epilogue: FP32 accumulators -> global ----
    int row0 = mt * 128 + warp_m * 64 + (lane >> 2);
    int col0 = nt * 256 + warp_n * 64 + (lane & 3) * 2;
#pragma unroll
    for (int mi = 0; mi < 4; mi++) {
#pragma unroll
        for (int nj = 0; nj < 8; nj++) {
            float* p0 = out + (size_t)(row0 + mi * 16) * OUTF + col0 + nj * 8;
            float* p1 = out + (size_t)(row0 + mi * 16 + 8) * OUTF + col0 + nj * 8;
            *reinterpret_cast<float2*>(p0) = make_float2(acc[mi][nj][0], acc[mi][nj][1]);
            *reinterpret_cast<float2*>(p1) = make_float2(acc[mi][nj][2], acc[mi][nj][3]);
        }
    }
}

// ---------------- host launch ----------------
extern "C" void kernel_launch(void* const* d_in, const int* in_sizes, int n_in,
                              void* d_out, int out_size) {
    (void)in_sizes; (void)n_in; (void)out_size;
    const float* x   = (const float*)d_in[0];
    const float* spw = (const float*)d_in[1];
    const float* baw = (const float*)d_in[2];
    float* out = (float*)d_out;

    prolog_ab<<<BLOCKS_A + BLOCKS_B, 256>>>(x, spw, baw);

    cudaFuncSetAttribute(kan_gemm, cudaFuncAttributeMaxDynamicSharedMemorySize, SMEM_NEED);
    kan_gemm<<<dim3(MT, NT), 256, SMEM_NEED>>>(out);
}

// round 15
// speedup vs baseline: 3.1445x; 1.0140x over previous
#include <cuda_runtime.h>
#include <cuda_fp16.h>
#include <cstdint>
#include <cstddef>

#define DI __device__ __forceinline__

// ---------------- problem constants ----------------
constexpr int BATCH = 4096;
constexpr int INF   = 1024;
constexpr int OUTF  = 1024;
constexpr int KSP   = INF * 8;       // 8192 spline K
constexpr int KTOT  = KSP + INF;     // 9216 total K
constexpr int KBLK  = 64;            // fp16 per K-tile -> 128 B rows (SW128)
constexpr int NKT   = KTOT / KBLK;   // 144 K-tiles
constexpr int TM    = 128;
constexpr int TN    = 256;           // proven best: operand reuse beats occupancy
constexpr int MT    = BATCH / TM;    // 32
constexpr int NT    = OUTF / TN;     // 4
constexpr int STAGES = 4;
constexpr int A_TILE_B = TM * KBLK * 2;       // 16384
constexpr int B_TILE_B = TN * KBLK * 2;       // 32768
constexpr int STAGE_B  = A_TILE_B + B_TILE_B; // 49152

constexpr int SOFF_FULL  = 0;    // 4 x 8B
constexpr int SOFF_EMPTY = 32;   // 4 x 8B
constexpr int SOFF_STAGE = 1024;
constexpr int SMEM_NEED  = 1024 + SOFF_STAGE + STAGES * STAGE_B; // 198656 < 227KB cap

constexpr int BLOCKS_A = (BATCH * INF) / 256;       // 16384
constexpr int BLOCKS_B = (OUTF * (KTOT / 8)) / 256; // 4608

// ---------------- scratch (device globals; no allocation) ----------------
__device__ __half g_A[(size_t)MT * NKT * TM * KBLK];  // 75.5 MB tiled+swizzled activations
__device__ __half g_B[(size_t)NT * NKT * TN * KBLK];  // 18.9 MB tiled+swizzled weights

// ---------------- PTX helpers ----------------
DI uint32_t s2u(const void* p) {
    uint32_t a;
    asm("{ .reg .u64 t; cvta.to.shared.u64 t, %1; cvt.u32.u64 %0, t; }" : "=r"(a) : "l"(p));
    return a;
}
DI uint32_t swz(uint32_t off) { return off ^ ((off >> 3) & 0x70); }

DI void mbar_init(uint32_t a, uint32_t cnt) {
    asm volatile("mbarrier.init.shared.b64 [%0], %1;" :: "r"(a), "r"(cnt) : "memory");
}
DI void mbar_arrive(uint32_t a) {
    asm volatile("mbarrier.arrive.release.cta.shared.b64 _, [%0];" :: "r"(a) : "memory");
}
DI void mbar_expect_tx(uint32_t a, uint32_t bytes) {
    asm volatile("mbarrier.arrive.expect_tx.shared.b64 _, [%0], %1;" :: "r"(a), "r"(bytes) : "memory");
}
DI void mbar_wait(uint32_t a, uint32_t parity) {
    asm volatile(
        "{\n\t"
        ".reg .pred P1;\n\t"
        "WAIT_LOOP_%=:\n\t"
        "mbarrier.try_wait.parity.acquire.cta.shared::cta.b64 P1, [%0], %1, 0x989680;\n\t"
        "@P1 bra.uni WAIT_DONE_%=;\n\t"
        "bra.uni WAIT_LOOP_%=;\n\t"
        "WAIT_DONE_%=:\n\t"
        "}"
        :: "r"(a), "r"(parity) : "memory");
}
DI void bulk_g2s(uint32_t dst, const void* src, uint32_t bytes, uint32_t mbar) {
    asm volatile(
        "cp.async.bulk.shared::cluster.global.mbarrier::complete_tx::bytes [%0], [%1], %2, [%3];"
        :: "r"(dst), "l"(src), "r"(bytes), "r"(mbar) : "memory");
}
DI void ldsm4(uint32_t* r, uint32_t addr) {
    asm volatile("ldmatrix.sync.aligned.m8n8.x4.shared.b16 {%0,%1,%2,%3}, [%4];"
                 : "=r"(r[0]), "=r"(r[1]), "=r"(r[2]), "=r"(r[3]) : "r"(addr));
}
DI void mma_f16(float* c, const uint32_t* a, uint32_t b0, uint32_t b1) {
    asm volatile(
        "mma.sync.aligned.m16n8k16.row.col.f32.f16.f16.f32 "
        "{%0,%1,%2,%3}, {%4,%5,%6,%7}, {%8,%9}, {%0,%1,%2,%3};"
        : "+f"(c[0]), "+f"(c[1]), "+f"(c[2]), "+f"(c[3])
        : "r"(a[0]), "r"(a[1]), "r"(a[2]), "r"(a[3]), "r"(b0), "r"(b1));
}

// ---------------- merged prologue: A (closed-form bases + silu) and B ----------------
__global__ void __launch_bounds__(256) prolog_ab(const float* __restrict__ x,
                                                 const float* __restrict__ spw,
                                                 const float* __restrict__ baw) {
    if (blockIdx.x < BLOCKS_A) {
        // ----- part A: one (b, i) per thread -----
        int idx = blockIdx.x * 256 + threadIdx.x;
        int b = idx >> 10;
        int i = idx & 1023;
        float xv = x[idx];

        // tanh(x) = 1 - 2/(e^{2x}+1)
        float t = 1.0f - __fdividef(2.0f, __expf(2.0f * xv) + 1.0f);

        // closed-form cubic B-spline: only 4 nonzero bases
        float sc = (t + 2.2f) * 2.5f;                  // interval coord, in [3, 8]
        int m = __float2int_rd(sc);
        m = max(3, min(7, m));                          // clamp (t = +-1 edges)
        float u = sc - (float)m;                        // [0, 1)
        float omu = 1.0f - u;
        float B0 = omu * omu * omu * (1.0f / 6.0f);
        float B3 = u * u * u * (1.0f / 6.0f);
        float B1 = (0.5f * u - 1.0f) * u * u + (2.0f / 3.0f);   // 0.5u^3 - u^2 + 2/3
        float B2 = 1.0f - B0 - B1 - B3;                // partition of unity
        int o = m - 3;                                  // 0..4: first nonzero basis index

        uint32_t hB01, hB23, hB_0, hB12, hB3_;
        {
            __half2 v;
            v = __floats2half2_rn(B0, B1);   hB01 = *reinterpret_cast<uint32_t*>(&v);
            v = __floats2half2_rn(B2, B3);   hB23 = *reinterpret_cast<uint32_t*>(&v);
            v = __floats2half2_rn(0.0f, B0); hB_0 = *reinterpret_cast<uint32_t*>(&v);
            v = __floats2half2_rn(B1, B2);   hB12 = *reinterpret_cast<uint32_t*>(&v);
            v = __floats2half2_rn(B3, 0.0f); hB3_ = *reinterpret_cast<uint32_t*>(&v);
        }
        uint4 out4;
        switch (o) {
            case 0:  out4 = make_uint4(hB01, hB23, 0u, 0u);   break;
            case 1:  out4 = make_uint4(hB_0, hB12, hB3_, 0u); break;
            case 2:  out4 = make_uint4(0u, hB01, hB23, 0u);   break;
            case 3:  out4 = make_uint4(0u, hB_0, hB12, hB3_); break;
            default: out4 = make_uint4(0u, 0u, hB01, hB23);   break;  // o==4
        }

        int mt = b >> 7, row = b & 127;
        char* abase = (char*)g_A;
        {
            int kt = i >> 3;
            size_t tile = ((size_t)(mt * NKT + kt)) * A_TILE_B;
            uint32_t off = (uint32_t)(row * 128 + (i & 7) * 16);
            *reinterpret_cast<uint4*>(abase + tile + swz(off)) = out4;
        }
        {
            float sl = __fdividef(xv, 1.0f + __expf(-xv));
            int kt = 128 + (i >> 6);
            size_t tile = ((size_t)(mt * NKT + kt)) * A_TILE_B;
            uint32_t off = (uint32_t)(row * 128 + (i & 63) * 2);
            *reinterpret_cast<__half*>(abase + tile + swz(off)) = __float2half_rn(sl);
        }
    } else {
        // ----- part B: one group of 8 K-floats per thread -----
        int idx = (blockIdx.x - BLOCKS_A) * 256 + threadIdx.x;
        int o  = idx / (KTOT / 8);
        int kq = idx % (KTOT / 8);
        int k  = kq * 8;
        float4 v0, v1;
        if (k < KSP) {
            const float4* p = reinterpret_cast<const float4*>(spw + (size_t)o * KSP + k);
            v0 = p[0]; v1 = p[1];
        } else {
            const float4* p = reinterpret_cast<const float4*>(baw + (size_t)o * INF + (k - KSP));
            v0 = p[0]; v1 = p[1];
        }
        __half hv[8];
        hv[0] = __float2half_rn(v0.x); hv[1] = __float2half_rn(v0.y);
        hv[2] = __float2half_rn(v0.z); hv[3] = __float2half_rn(v0.w);
        hv[4] = __float2half_rn(v1.x); hv[5] = __float2half_rn(v1.y);
        hv[6] = __float2half_rn(v1.z); hv[7] = __float2half_rn(v1.w);

        int nt = o >> 8, row = o & 255;   // TN=256 tiles
        int kt = k >> 6;
        size_t tile = ((size_t)(nt * NKT + kt)) * B_TILE_B;
        uint32_t off = (uint32_t)(row * 128 + (k & 63) * 2);
        *reinterpret_cast<uint4*>((char*)g_B + tile + swz(off)) = *reinterpret_cast<uint4*>(hv);
    }
}

// ---------------- GEMM: mma.sync fp16, 128x256, rotating producer warp ----------------
// ks==3 seam reordering: issue half the final MMA batch BEFORE the cross-tile
// full-wait (keeps the tensor pipe fed if the wait blocks), prefetch the next
// tile's fragments, then issue the other half (hides LDSM latency).
__global__ void __launch_bounds__(256, 1) kan_gemm(float* __restrict__ out) {
    extern __shared__ __align__(16) char smem_raw[];
    uint32_t sb = (s2u(smem_raw) + 1023u) & ~1023u;
    int tid = threadIdx.x, wid = tid >> 5, lane = tid & 31;
    int warp_m = wid >> 2, warp_n = wid & 3;   // 2 x 4 warp grid, 64x64 per warp

    if (tid == 0) {
        for (int s = 0; s < STAGES; s++) {
            mbar_init(sb + SOFF_FULL  + 8 * s, 1);   // tx-gated fill
            mbar_init(sb + SOFF_EMPTY + 8 * s, 8);   // one elected arrive per warp
        }
    }
    __syncthreads();

    int mt = blockIdx.x, nt = blockIdx.y;
    const char* agl = (const char*)g_A + (size_t)mt * NKT * A_TILE_B;
    const char* bgl = (const char*)g_B + (size_t)nt * NKT * B_TILE_B;

    // ---- per-thread ldmatrix addressing (swizzle-folded) ----
    int g = lane >> 3, r = lane & 7;
    int rA = warp_m * 64 + (g & 1) * 8 + r;
    uint32_t acol0 = (uint32_t)((g >> 1) * 16);
    uint32_t amask = (uint32_t)((rA & 7) << 4);
    int rB = warp_n * 64 + ((g >> 1) & 1) * 8 + r;
    uint32_t bcol0 = (uint32_t)((g & 1) * 16);
    uint32_t bmask = (uint32_t)((rB & 7) << 4);
    uint32_t acol[4], bcol[4];
#pragma unroll
    for (int ks = 0; ks < 4; ks++) {
        acol[ks] = (acol0 + ks * 32) ^ amask;
        bcol[ks] = (bcol0 + ks * 32) ^ bmask;
    }
    uint32_t aRowOff = (uint32_t)(rA * 128);
    uint32_t bRowOff = (uint32_t)(A_TILE_B + rB * 128);

    float acc[4][8][4];
#pragma unroll
    for (int mi = 0; mi < 4; mi++)
#pragma unroll
        for (int nj = 0; nj < 8; nj++)
#pragma unroll
            for (int q = 0; q < 4; q++) acc[mi][nj][q] = 0.0f;

    // ---- prefetch first STAGES-1 tiles (warp 0 lane 0; no prior waits needed) ----
    if (tid == 0) {
#pragma unroll
        for (int p = 0; p < STAGES - 1; p++) {
            uint32_t full = sb + SOFF_FULL + 8 * p;
            mbar_expect_tx(full, STAGE_B);
            uint32_t sa = sb + SOFF_STAGE + p * STAGE_B;
            bulk_g2s(sa,            agl + (size_t)p * A_TILE_B, A_TILE_B, full);
            bulk_g2s(sa + A_TILE_B, bgl + (size_t)p * B_TILE_B, B_TILE_B, full);
        }
    }

    // ---- pipeline prologue: wait stage 0, load its ks=0 fragments ----
    uint32_t af[2][4][4], bf[2][4][4];
    mbar_wait(sb + SOFF_FULL + 0, 0);
    {
        uint32_t baseA = sb + SOFF_STAGE + aRowOff;
        uint32_t baseB = sb + SOFF_STAGE + bRowOff;
#pragma unroll
        for (int mi = 0; mi < 4; mi++) ldsm4(af[0][mi], baseA + mi * 2048 + acol[0]);
#pragma unroll
        for (int np = 0; np < 4; np++) ldsm4(bf[0][np], baseB + np * 2048 + bcol[0]);
    }

#pragma unroll 1
    for (int kt = 0; kt < NKT; kt++) {
        // ---- rotating producer: warp (kt & 7), lane 0 handles tile kt+3 ----
        if (wid == (kt & 7) && lane == 0) {
            int j = kt + STAGES - 1;
            if (j < NKT) {
                int sp = j & (STAGES - 1);
                if (j >= STAGES) {
                    // parity of empty[sp] for the (j>>2)-th occupancy
                    mbar_wait(sb + SOFF_EMPTY + 8 * sp, ((j >> 2) & 1) ^ 1);
                }
                uint32_t full = sb + SOFF_FULL + 8 * sp;
                mbar_expect_tx(full, STAGE_B);
                uint32_t sa = sb + SOFF_STAGE + sp * STAGE_B;
                bulk_g2s(sa,            agl + (size_t)j * A_TILE_B, A_TILE_B, full);
                bulk_g2s(sa + A_TILE_B, bgl + (size_t)j * B_TILE_B, B_TILE_B, full);
            }
        }
        int s = kt & (STAGES - 1);
        uint32_t sbase = sb + SOFF_STAGE + s * STAGE_B;
        uint32_t baseA = sbase + aRowOff;
        uint32_t baseB = sbase + bRowOff;

        // ---- ks = 0..2: prefetch ks+1 fragments, then 32 MMAs ----
#pragma unroll
        for (int ks = 0; ks < 3; ks++) {
            int cur = ks & 1, nxt = cur ^ 1;
#pragma unroll
            for (int mi = 0; mi < 4; mi++) ldsm4(af[nxt][mi], baseA + mi * 2048 + acol[ks + 1]);
#pragma unroll
            for (int np = 0; np < 4; np++) ldsm4(bf[nxt][np], baseB + np * 2048 + bcol[ks + 1]);
            // warp's stage-s LDSMs all complete here (ldmatrix is warp-collective)
            if (ks == 2 && lane == 0) mbar_arrive(sb + SOFF_EMPTY + 8 * s);
#pragma unroll
            for (int mi = 0; mi < 4; mi++)
#pragma unroll
                for (int nj = 0; nj < 8; nj++)
                    mma_f16(acc[mi][nj], af[cur][mi],
                            bf[cur][nj >> 1][(nj & 1) * 2], bf[cur][nj >> 1][(nj & 1) * 2 + 1]);
        }

        // ---- ks = 3 (cur=1, nxt=0): split MMA batch around the cross-tile wait ----
        {
            // first half: keep the tensor pipe fed while the wait may block
#pragma unroll
            for (int mi = 0; mi < 2; mi++)
#pragma unroll
                for (int nj = 0; nj < 8; nj++)
                    mma_f16(acc[mi][nj], af[1][mi],
                            bf[1][nj >> 1][(nj & 1) * 2], bf[1][nj >> 1][(nj & 1) * 2 + 1]);
            if (kt + 1 < NKT) {
                int kn = kt + 1;
                int s2 = kn & (STAGES - 1);
                mbar_wait(sb + SOFF_FULL + 8 * s2, (kn >> 2) & 1);
                uint32_t nbase = sb + SOFF_STAGE + s2 * STAGE_B;
#pragma unroll
                for (int mi = 0; mi < 4; mi++) ldsm4(af[0][mi], nbase + aRowOff + mi * 2048 + acol[0]);
#pragma unroll
                for (int np = 0; np < 4; np++) ldsm4(bf[0][np], nbase + bRowOff + np * 2048 + bcol[0]);
            }
            // second half: hides the prefetch LDSM latency
#pragma unroll
            for (int mi = 2; mi < 4; mi++)
#pragma unroll
                for (int nj = 0; nj < 8; nj++)
                    mma_f16(acc[mi][nj], af[1][mi],
                            bf[1][nj >> 1][(nj & 1) * 2], bf[1][nj >> 1][(nj & 1) * 2 + 1]);
        }
    }

    // ---- epilogue: FP32 accumulators -> global ----
    int row0 = mt * 128 + warp_m * 64 + (lane >> 2);
    int col0 = nt * 256 + warp_n * 64 + (lane & 3) * 2;
#pragma unroll
    for (int mi = 0; mi < 4; mi++) {
#pragma unroll
        for (int nj = 0; nj < 8; nj++) {
            float* p0 = out + (size_t)(row0 + mi * 16) * OUTF + col0 + nj * 8;
            float* p1 = out + (size_t)(row0 + mi * 16 + 8) * OUTF + col0 + nj * 8;
            *reinterpret_cast<float2*>(p0) = make_float2(acc[mi][nj][0], acc[mi][nj][1]);
            *reinterpret_cast<float2*>(p1) = make_float2(acc[mi][nj][2], acc[mi][nj][3]);
        }
    }
}

// ---------------- host launch ----------------
extern "C" void kernel_launch(void* const* d_in, const int* in_sizes, int n_in,
                              void* d_out, int out_size) {
    (void)in_sizes; (void)n_in; (void)out_size;
    const float* x   = (const float*)d_in[0];
    const float* spw = (const float*)d_in[1];
    const float* baw = (const float*)d_in[2];
    float* out = (float*)d_out;

    prolog_ab<<<BLOCKS_A + BLOCKS_B, 256>>>(x, spw, baw);

    cudaFuncSetAttribute(kan_gemm, cudaFuncAttributeMaxDynamicSharedMemorySize, SMEM_NEED);
    kan_gemm<<<dim3(MT, NT), 256, SMEM_NEED>>>(out);
}